// round 15
// baseline (speedup 1.0000x reference)
#include <cuda_runtime.h>
#include <cstdint>

#define NF 255
#define NH 128
#define NC 16
#define NIMG 64
#define PI2 6.28318530717958647692f

__device__ __forceinline__ uint32_t f2tf(float x){
    uint32_t r; asm("cvt.rna.tf32.f32 %0, %1;" : "=r"(r) : "f"(x)); return r;
}
__device__ __forceinline__ float2 spl(float x){
    uint32_t h = f2tf(x);
    float hf = __uint_as_float(h);
    uint32_t l = f2tf(x - hf);
    return make_float2(hf, __uint_as_float(l));
}
__device__ __forceinline__ void mmaT(float* c, const uint32_t* a, const uint32_t* b){
    asm("mma.sync.aligned.m16n8k8.row.col.f32.tf32.tf32.f32 "
        "{%0,%1,%2,%3},{%4,%5,%6,%7},{%8,%9},{%0,%1,%2,%3};"
        : "+f"(c[0]),"+f"(c[1]),"+f"(c[2]),"+f"(c[3])
        : "r"(a[0]),"r"(a[1]),"r"(a[2]),"r"(a[3]),"r"(b[0]),"r"(b[1]));
}
__device__ __forceinline__ void mma3(float* c, const uint32_t* ah, const uint32_t* al,
                                     const uint32_t* bh, const uint32_t* bl){
    mmaT(c, ah, bh); mmaT(c, ah, bl); mmaT(c, al, bh);
}
// A fragment (m16 x k8) from (hi,lo) float2 plane, pitch 20 float2
__device__ __forceinline__ void ldA(uint32_t* h, uint32_t* l, const float2* P, int m, int k){
    float2 v0=P[m*20+k],     v1=P[(m+8)*20+k];
    float2 v2=P[m*20+k+4],   v3=P[(m+8)*20+k+4];
    h[0]=__float_as_uint(v0.x); l[0]=__float_as_uint(v0.y);
    h[1]=__float_as_uint(v1.x); l[1]=__float_as_uint(v1.y);
    h[2]=__float_as_uint(v2.x); l[2]=__float_as_uint(v2.y);
    h[3]=__float_as_uint(v3.x); l[3]=__float_as_uint(v3.y);
}
__device__ __forceinline__ void ldB(uint32_t* h, uint32_t* l, const float2* P, int n, int k){
    float2 v0=P[n*20+k], v1=P[n*20+k+4];
    h[0]=__float_as_uint(v0.x); l[0]=__float_as_uint(v0.y);
    h[1]=__float_as_uint(v1.x); l[1]=__float_as_uint(v1.y);
}

// scratch (device globals: allocation-free rule)
__device__ float2 g_Fp[NF*NH];          // (cos,-sin)[v*128+h]
__device__ float2 g_Gp[NH*NF];          // (cos, sin)[w'*255+v], crop +63
__device__ float2 g_Ep[NH*NH];          // (cu*cos, -cu*sin)[h*128+u]
__device__ float  g_xT[NIMG*NH*NH];     // [img][w][h]
__device__ float2 g_A [NIMG*NH*NH];     // [img][u][w]
__device__ float2 g_Xf[NIMG*NH*NF];     // [img][u][v]
__device__ float2 g_Kh[NC*NH*NF];       // [c][u][v] folded, scaled
__device__ float2 g_St[NIMG*NH*NH];     // [img][w'][u] (transposed)

__global__ void k_twiddles(){
    int i = blockIdx.x*blockDim.x + threadIdx.x;
    const float w0 = PI2/255.0f;
    if(i < NF*NH){
        int v=i/NH, h=i%NH; float a=w0*(float)((v*h)%NF);
        g_Fp[i]=make_float2(cosf(a),-sinf(a)); return;
    }
    int j=i-NF*NH;
    if(j < NH*NF){
        int wq=j/NF, v=j%NF; float a=w0*(float)((v*(wq+63))%NF);
        g_Gp[j]=make_float2(cosf(a),sinf(a)); return;
    }
    int e=j-NH*NF;
    if(e < NH*NH){
        int h=e/NH, u=e%NH; float a=w0*(float)((u*(h+63))%NF);
        float cu = u?2.f:1.f;
        g_Ep[e]=make_float2(cu*cosf(a), -cu*sinf(a));
    }
}

// in[b][h][w][c] -> g_xT[(b*16+c)][w][h], smem-staged
__global__ void k_transpose(const float* __restrict__ in){
    __shared__ float ts[NC*16*36];
    const int b=blockIdx.z, h0=blockIdx.y*32, w0=blockIdx.x*16, tid=threadIdx.x;
#pragma unroll
    for(int it=0;it<2;it++){
        int p=tid+it*256, h=p>>4, w=p&15;
        const float4* src=(const float4*)(in+(size_t)((b*NH+h0+h)*NH+w0+w)*NC);
#pragma unroll
        for(int q=0;q<4;q++){
            float4 v=src[q]; int cb=q*4;
            ts[(cb+0)*576+w*36+h]=v.x; ts[(cb+1)*576+w*36+h]=v.y;
            ts[(cb+2)*576+w*36+h]=v.z; ts[(cb+3)*576+w*36+h]=v.w;
        }
    }
    __syncthreads();
    int h4=(tid&7)*4;
#pragma unroll
    for(int it=0;it<8;it++){
        int q=(tid>>3)+it*32, c=q>>4, w=q&15;
        float4 v=*(const float4*)&ts[c*576+w*36+h4];
        *(float4*)&g_xT[(size_t)((b*NC+c)*NH+w0+w)*NH+h0+h4]=v;
    }
}

// fused Keff (sum over cout) + Hermitian fold + 1/255^2 scale
__global__ void k_keffkh(const float* __restrict__ kr, const float* __restrict__ ki){
    int idx = blockIdx.x*blockDim.x + threadIdx.x;
    if(idx >= NH*NF*NC) return;
    int c = idx&15, v = (idx>>4)%NF, u = idx/(16*NF);
    int u2=(NF-u)%NF, v2=(NF-v)%NF;
    size_t p1=((size_t)(u*NF+v)*NC+c)*16, p2=((size_t)(u2*NF+v2)*NC+c)*16;
    float sr1=0,si1=0,sr2=0,si2=0; const float4* a;
    a=(const float4*)(kr+p1);
#pragma unroll
    for(int j=0;j<4;j++){float4 t=a[j];sr1+=t.x+t.y+t.z+t.w;}
    a=(const float4*)(ki+p1);
#pragma unroll
    for(int j=0;j<4;j++){float4 t=a[j];si1+=t.x+t.y+t.z+t.w;}
    a=(const float4*)(kr+p2);
#pragma unroll
    for(int j=0;j<4;j++){float4 t=a[j];sr2+=t.x+t.y+t.z+t.w;}
    a=(const float4*)(ki+p2);
#pragma unroll
    for(int j=0;j<4;j++){float4 t=a[j];si2+=t.x+t.y+t.z+t.w;}
    const float s = 0.5f/65025.0f;
    g_Kh[(c*NH+u)*NF+v]=make_float2(s*(sr1+sr2), s*(si1-si2));
}

// ---------------------------------------------------------------------------
// Tensor GEMMs: CTA 32m x 64n, 128 thr.
// Warp w: m-stripe mw=(w>>1)*16, n-half nh=(w&1)*32 -> m16 x n32, 4 n8-blocks.
// BK=16, smem planes = (tf32-hi, tf32-lo) pairs, 3xTF32 mma m16n8k8.
// Stages 2/3: Karatsuba (P1,P2,P3) -> 9 mmaT per n8-block per k8.
// ---------------------------------------------------------------------------

// Stage1: A[img][u][w] = sum_h F[u][h]*x[img][w][h]  (cplx A, real B)
__global__ void __launch_bounds__(128) k_stage1(){
    __shared__ float2 AR[32*20], AI[32*20], BRp[64*20];
    const int img=blockIdx.z, n0=blockIdx.x*64, m0=blockIdx.y*32, tid=threadIdx.x;
    const int lane=tid&31, gl=lane>>2, cl=lane&3;
    const int wid=tid>>5, mw=(wid>>1)*16, nh=(wid&1)*32;
    const int lk=tid&15, lr=tid>>4;
    const float* Bg = g_xT + img*NH*NH;
    float cR[4][4], cI[4][4];
#pragma unroll
    for(int i=0;i<4;i++)
#pragma unroll
        for(int j=0;j<4;j++){ cR[i][j]=0.f; cI[i][j]=0.f; }
    float2 pa[4]; float pbx[8];
#pragma unroll
    for(int r=0;r<4;r++) pa[r]=g_Fp[(m0+lr+r*8)*NH+lk];
#pragma unroll
    for(int r=0;r<8;r++) pbx[r]=Bg[(n0+lr+r*8)*NH+lk];
    for(int t=0;t<8;t++){
#pragma unroll
        for(int r=0;r<4;r++){ int m=lr+r*8;
            AR[m*20+lk]=spl(pa[r].x); AI[m*20+lk]=spl(pa[r].y); }
#pragma unroll
        for(int r=0;r<8;r++) BRp[(lr+r*8)*20+lk]=spl(pbx[r]);
        __syncthreads();
        if(t<7){
            int k0=(t+1)*16;
#pragma unroll
            for(int r=0;r<4;r++) pa[r]=g_Fp[(m0+lr+r*8)*NH+k0+lk];
#pragma unroll
            for(int r=0;r<8;r++) pbx[r]=Bg[(n0+lr+r*8)*NH+k0+lk];
        }
#pragma unroll
        for(int s=0;s<16;s+=8){
            uint32_t arh[4],arl[4],aih[4],ail[4];
            ldA(arh,arl,AR,mw+gl,s+cl);
            ldA(aih,ail,AI,mw+gl,s+cl);
#pragma unroll
            for(int nb=0;nb<4;nb++){
                uint32_t brh[2],brl[2];
                ldB(brh,brl,BRp,nh+nb*8+gl,s+cl);
                mma3(cR[nb],arh,arl,brh,brl);
                mma3(cI[nb],aih,ail,brh,brl);
            }
        }
        __syncthreads();
    }
    float2* C = g_A + img*NH*NH;
#pragma unroll
    for(int nb=0;nb<4;nb++){
        int n = n0+nh+nb*8+2*cl, m = m0+mw+gl;
        C[m*NH+n]       = make_float2(cR[nb][0],cI[nb][0]);
        C[m*NH+n+1]     = make_float2(cR[nb][1],cI[nb][1]);
        C[(m+8)*NH+n]   = make_float2(cR[nb][2],cI[nb][2]);
        C[(m+8)*NH+n+1] = make_float2(cR[nb][3],cI[nb][3]);
    }
}

// Stage2 (Karatsuba): Xf[img][u][v] = sum_w A[img][u][w]*F[v][w]
__global__ void __launch_bounds__(128) k_stage2(){
    __shared__ float2 AR[32*20], AI[32*20], AS[32*20];
    __shared__ float2 BR[64*20], BI[64*20], BS[64*20];
    const int img=blockIdx.z, n0=blockIdx.x*64, m0=blockIdx.y*32, tid=threadIdx.x;
    const int lane=tid&31, gl=lane>>2, cl=lane&3;
    const int wid=tid>>5, mw=(wid>>1)*16, nh=(wid&1)*32;
    const int lk=tid&15, lr=tid>>4;
    const float2* Ag = g_A + img*NH*NH;
    float c1[4][4], c2[4][4], c3[4][4];
#pragma unroll
    for(int i=0;i<4;i++)
#pragma unroll
        for(int j=0;j<4;j++){ c1[i][j]=0.f; c2[i][j]=0.f; c3[i][j]=0.f; }
    float2 pa[4], pb[8];
#pragma unroll
    for(int r=0;r<4;r++) pa[r]=Ag[(m0+lr+r*8)*NH+lk];
#pragma unroll
    for(int r=0;r<8;r++){ int v=n0+lr+r*8;
        pb[r]=(v<NF)? g_Fp[v*NH+lk] : make_float2(0.f,0.f); }
    for(int t=0;t<8;t++){
#pragma unroll
        for(int r=0;r<4;r++){ int m=lr+r*8;
            AR[m*20+lk]=spl(pa[r].x); AI[m*20+lk]=spl(pa[r].y);
            AS[m*20+lk]=spl(pa[r].x+pa[r].y); }
#pragma unroll
        for(int r=0;r<8;r++){ int n=lr+r*8;
            BR[n*20+lk]=spl(pb[r].x); BI[n*20+lk]=spl(pb[r].y);
            BS[n*20+lk]=spl(pb[r].x+pb[r].y); }
        __syncthreads();
        if(t<7){
            int k0=(t+1)*16;
#pragma unroll
            for(int r=0;r<4;r++) pa[r]=Ag[(m0+lr+r*8)*NH+k0+lk];
#pragma unroll
            for(int r=0;r<8;r++){ int v=n0+lr+r*8;
                pb[r]=(v<NF)? g_Fp[v*NH+k0+lk] : make_float2(0.f,0.f); }
        }
#pragma unroll
        for(int s=0;s<16;s+=8){
            uint32_t arh[4],arl[4],aih[4],ail[4],ash[4],asl[4];
            ldA(arh,arl,AR,mw+gl,s+cl);
            ldA(aih,ail,AI,mw+gl,s+cl);
            ldA(ash,asl,AS,mw+gl,s+cl);
#pragma unroll
            for(int nb=0;nb<4;nb++){
                uint32_t brh[2],brl[2],bih[2],bil[2],bsh[2],bsl[2];
                ldB(brh,brl,BR,nh+nb*8+gl,s+cl);
                ldB(bih,bil,BI,nh+nb*8+gl,s+cl);
                ldB(bsh,bsl,BS,nh+nb*8+gl,s+cl);
                mma3(c1[nb],arh,arl,brh,brl);   // P1 = Ar*Br
                mma3(c2[nb],aih,ail,bih,bil);   // P2 = Ai*Bi
                mma3(c3[nb],ash,asl,bsh,bsl);   // P3 = (Ar+Ai)(Br+Bi)
            }
        }
        __syncthreads();
    }
    float2* C = g_Xf + img*NH*NF;
#pragma unroll
    for(int nb=0;nb<4;nb++){
        int n = n0+nh+nb*8+2*cl, m = m0+mw+gl;
#pragma unroll
        for(int q=0;q<4;q++){
            int nn = n + (q&1), mm = m + (q>>1)*8;
            if(nn<NF){
                float re = c1[nb][q]-c2[nb][q];
                float im = c3[nb][q]-c1[nb][q]-c2[nb][q];
                C[mm*NF+nn]=make_float2(re,im);
            }
        }
    }
}

// Stage3 (Karatsuba): St[img][w'][u] = sum_v (Xf[u][v]*Kh[c][u][v])*G[w'][v]
__global__ void __launch_bounds__(128) k_stage3(){
    __shared__ float2 AR[32*20], AI[32*20], AS[32*20];
    __shared__ float2 BR[64*20], BI[64*20], BS[64*20];
    const int img=blockIdx.z, c=img&15, n0=blockIdx.x*64, m0=blockIdx.y*32, tid=threadIdx.x;
    const int lane=tid&31, gl=lane>>2, cl=lane&3;
    const int wid=tid>>5, mw=(wid>>1)*16, nh=(wid&1)*32;
    const int lk=tid&15, lr=tid>>4;
    const float2* Xg = g_Xf + img*NH*NF;
    const float2* Kg = g_Kh + c*NH*NF;
    float c1[4][4], c2[4][4], c3[4][4];
#pragma unroll
    for(int i=0;i<4;i++)
#pragma unroll
        for(int j=0;j<4;j++){ c1[i][j]=0.f; c2[i][j]=0.f; c3[i][j]=0.f; }
    float2 py[4], pb[8];
    {
        int kk=lk; bool ok=(kk<NF);
#pragma unroll
        for(int r=0;r<4;r++){
            float yr=0.f, yi=0.f;
            if(ok){ float2 x=Xg[(m0+lr+r*8)*NF+kk], h=Kg[(m0+lr+r*8)*NF+kk];
                yr=x.x*h.x-x.y*h.y; yi=x.x*h.y+x.y*h.x; }
            py[r]=make_float2(yr,yi);
        }
#pragma unroll
        for(int r=0;r<8;r++)
            pb[r]= ok ? g_Gp[(n0+lr+r*8)*NF+kk] : make_float2(0.f,0.f);
    }
    for(int t=0;t<16;t++){
#pragma unroll
        for(int r=0;r<4;r++){ int m=lr+r*8;
            AR[m*20+lk]=spl(py[r].x); AI[m*20+lk]=spl(py[r].y);
            AS[m*20+lk]=spl(py[r].x+py[r].y); }
#pragma unroll
        for(int r=0;r<8;r++){ int n=lr+r*8;
            BR[n*20+lk]=spl(pb[r].x); BI[n*20+lk]=spl(pb[r].y);
            BS[n*20+lk]=spl(pb[r].x+pb[r].y); }
        __syncthreads();
        if(t<15){
            int kk=(t+1)*16+lk; bool ok=(kk<NF);
#pragma unroll
            for(int r=0;r<4;r++){
                float yr=0.f, yi=0.f;
                if(ok){ float2 x=Xg[(m0+lr+r*8)*NF+kk], h=Kg[(m0+lr+r*8)*NF+kk];
                    yr=x.x*h.x-x.y*h.y; yi=x.x*h.y+x.y*h.x; }
                py[r]=make_float2(yr,yi);
            }
#pragma unroll
            for(int r=0;r<8;r++)
                pb[r]= ok ? g_Gp[(n0+lr+r*8)*NF+kk] : make_float2(0.f,0.f);
        }
#pragma unroll
        for(int s=0;s<16;s+=8){
            uint32_t arh[4],arl[4],aih[4],ail[4],ash[4],asl[4];
            ldA(arh,arl,AR,mw+gl,s+cl);
            ldA(aih,ail,AI,mw+gl,s+cl);
            ldA(ash,asl,AS,mw+gl,s+cl);
#pragma unroll
            for(int nb=0;nb<4;nb++){
                uint32_t brh[2],brl[2],bih[2],bil[2],bsh[2],bsl[2];
                ldB(brh,brl,BR,nh+nb*8+gl,s+cl);
                ldB(bih,bil,BI,nh+nb*8+gl,s+cl);
                ldB(bsh,bsl,BS,nh+nb*8+gl,s+cl);
                mma3(c1[nb],arh,arl,brh,brl);
                mma3(c2[nb],aih,ail,bih,bil);
                mma3(c3[nb],ash,asl,bsh,bsl);
            }
        }
        __syncthreads();
    }
    float2* C = g_St + img*NH*NH;
#pragma unroll
    for(int nb=0;nb<4;nb++){            // store transposed: C[w'][u]
        int n = n0+nh+nb*8+2*cl, m = m0+mw+gl;
#pragma unroll
        for(int q=0;q<4;q++){
            int nn = n + (q&1), mm = m + (q>>1)*8;
            float re = c1[nb][q]-c2[nb][q];
            float im = c3[nb][q]-c1[nb][q]-c2[nb][q];
            C[nn*NH+mm]=make_float2(re,im);
        }
    }
}

// Stage4: out[b][h][w][c] = bias[c] + sum_u (Er[h][u]*Sr[w][u] - Ei[h][u]*Si[w][u])
__global__ void __launch_bounds__(128) k_stage4(const float* __restrict__ bias,
                                               float* __restrict__ out){
    __shared__ float2 AE[32*20], AN[32*20], BR[64*20], BI[64*20];
    const int img=blockIdx.z, b2=img>>4, c=img&15;
    const int n0=blockIdx.x*64, m0=blockIdx.y*32, tid=threadIdx.x;
    const int lane=tid&31, gl=lane>>2, cl=lane&3;
    const int wid=tid>>5, mw=(wid>>1)*16, nh=(wid&1)*32;
    const int lk=tid&15, lr=tid>>4;
    const float2* Sg = g_St + img*NH*NH;
    float cO[4][4];
#pragma unroll
    for(int i=0;i<4;i++)
#pragma unroll
        for(int j=0;j<4;j++) cO[i][j]=0.f;
    float2 pe[4], ps[8];
#pragma unroll
    for(int r=0;r<4;r++) pe[r]=g_Ep[(m0+lr+r*8)*NH+lk];
#pragma unroll
    for(int r=0;r<8;r++) ps[r]=Sg[(n0+lr+r*8)*NH+lk];
    for(int t=0;t<8;t++){
#pragma unroll
        for(int r=0;r<4;r++){ int m=lr+r*8;
            AE[m*20+lk]=spl(pe[r].x); AN[m*20+lk]=spl(pe[r].y); }   // (er, -ei)
#pragma unroll
        for(int r=0;r<8;r++){ int n=lr+r*8;
            BR[n*20+lk]=spl(ps[r].x); BI[n*20+lk]=spl(ps[r].y); }
        __syncthreads();
        if(t<7){
            int k0=(t+1)*16;
#pragma unroll
            for(int r=0;r<4;r++) pe[r]=g_Ep[(m0+lr+r*8)*NH+k0+lk];
#pragma unroll
            for(int r=0;r<8;r++) ps[r]=Sg[(n0+lr+r*8)*NH+k0+lk];
        }
#pragma unroll
        for(int s=0;s<16;s+=8){
            uint32_t aeh[4],ael[4],anh[4],anl[4];
            ldA(aeh,ael,AE,mw+gl,s+cl);
            ldA(anh,anl,AN,mw+gl,s+cl);
#pragma unroll
            for(int nb=0;nb<4;nb++){
                uint32_t brh[2],brl[2],bih[2],bil[2];
                ldB(brh,brl,BR,nh+nb*8+gl,s+cl);
                ldB(bih,bil,BI,nh+nb*8+gl,s+cl);
                mma3(cO[nb],aeh,ael,brh,brl);   // + er*Sr
                mma3(cO[nb],anh,anl,bih,bil);   // + (-ei)*Si
            }
        }
        __syncthreads();
    }
    float bv = bias[c];
#pragma unroll
    for(int nb=0;nb<4;nb++){
        int w = n0+nh+nb*8+2*cl, h = m0+mw+gl;
        out[((size_t)((b2*NH+h)*NH+w  ))*NC+c] = cO[nb][0]+bv;
        out[((size_t)((b2*NH+h)*NH+w+1))*NC+c] = cO[nb][1]+bv;
        out[((size_t)((b2*NH+h+8)*NH+w  ))*NC+c] = cO[nb][2]+bv;
        out[((size_t)((b2*NH+h+8)*NH+w+1))*NC+c] = cO[nb][3]+bv;
    }
}

extern "C" void kernel_launch(void* const* d_in, const int* in_sizes, int n_in,
                              void* d_out, int out_size){
    const float* inp  = (const float*)d_in[0];
    const float* kr   = (const float*)d_in[1];
    const float* ki   = (const float*)d_in[2];
    const float* bias = (const float*)d_in[3];
    float* out = (float*)d_out;

    const int twN = NF*NH + NH*NF + NH*NH;
    k_twiddles<<<(twN+255)/256, 256>>>();
    dim3 tg(8,4,4);
    k_transpose<<<tg, 256>>>(inp);
    k_keffkh<<<(NH*NF*NC+255)/256, 256>>>(kr, ki);

    dim3 blk(128);
    dim3 g1(2,4,NIMG); k_stage1<<<g1, blk>>>();
    dim3 g2(4,4,NIMG); k_stage2<<<g2, blk>>>();
    dim3 g3(2,4,NIMG); k_stage3<<<g3, blk>>>();
    dim3 g4(2,4,NIMG); k_stage4<<<g4, blk>>>(bias, out);
}